// round 13
// baseline (speedup 1.0000x reference)
#include <cuda_runtime.h>

#define N_NODES 50000
#define N_EDGES 200000
#define IN_F 32
#define HID 32
#define N_GRAPHS 64
#define NBINS 65
#define EB 256                 // edges per block
#define NEBLK ((N_EDGES + EB - 1) / EB)
#define HB_BLOCKS (NEBLK + NBINS)

// ---------------- scratch (no allocs allowed; zero-init at load) ------------
__device__ float g_agg[N_NODES * HID];   // restored to 0 by node_kernel
__device__ float g_cnt[N_NODES];         // restored to 0 by node_kernel
__device__ float g_P[NBINS * 1024];
__device__ float g_Q[NBINS * 1024];
__device__ int   g_bhist[NBINS * NEBLK];
__device__ int   g_btot[NBINS];
__device__ int   g_sr[N_EDGES];      // s | (local_rank << 8)
__device__ int   g_perm[N_EDGES];    // e | (s << 18)
__device__ int   g_gs[N_GRAPHS];
__device__ int   g_ge[N_GRAPHS];

__device__ __forceinline__ float inf_f() { return __int_as_float(0x7f800000); }
__device__ __forceinline__ float key_of(float w, float b) {
    return (w != 0.f) ? (-b / w) : inf_f();
}
__device__ __forceinline__ unsigned f2tf32(float f) {
    unsigned r;
    asm("cvt.rna.tf32.f32 %0, %1;" : "=r"(r) : "f"(f));
    return r;
}
__device__ __forceinline__ void red_add_v4(float* p, float a, float b, float c, float d) {
    asm volatile("red.global.add.v4.f32 [%0], {%1,%2,%3,%4};"
                 :: "l"(p), "f"(a), "f"(b), "f"(c), "f"(d) : "memory");
}

#define MMA_ACC(C, a0, a1, a2, a3, B0, B1)                                      \
    asm volatile("mma.sync.aligned.m16n8k8.row.col.f32.tf32.tf32.f32 "          \
                 "{%0,%1,%2,%3}, {%4,%5,%6,%7}, {%8,%9}, {%0,%1,%2,%3};"        \
                 : "+f"((C)[0]), "+f"((C)[1]), "+f"((C)[2]), "+f"((C)[3])       \
                 : "r"(a0), "r"(a1), "r"(a2), "r"(a3), "r"(B0), "r"(B1))

#define MMA_SET(C, a0, a1, a2, a3, B0, B1)                                      \
    asm volatile("mma.sync.aligned.m16n8k8.row.col.f32.tf32.tf32.f32 "          \
                 "{%0,%1,%2,%3}, {%4,%5,%6,%7}, {%8,%9}, {%10,%11,%12,%13};"    \
                 : "=f"((C)[0]), "=f"((C)[1]), "=f"((C)[2]), "=f"((C)[3])       \
                 : "r"(a0), "r"(a1), "r"(a2), "r"(a3), "r"(B0), "r"(B1),        \
                   "f"(0.f), "f"(0.f), "f"(0.f), "f"(0.f))

// ---------------- K1: fused hist + build ------------------------------------
__global__ void __launch_bounds__(256) histbuild_kernel(
    const float* __restrict__ ea, const int* __restrict__ batch,
    const float* __restrict__ w1, const float* __restrict__ b1,
    const float* __restrict__ w2, const float* __restrict__ b2)
{
    __shared__ float key[64], srt[64], wa[64], ba[64];
    __shared__ int lh[NBINS];
    const int t = threadIdx.x;
    const int b = blockIdx.x;

    if (t < 64) key[t] = key_of(w1[t], b1[t]);
    if (t < NBINS) lh[t] = 0;
    __syncthreads();
    if (t < 64) {
        float kt = key[t];
        int r = 0;
        #pragma unroll
        for (int k = 0; k < 64; k++) {
            float kk = key[k];
            r += (kk < kt) || (kk == kt && k < t);
        }
        srt[r] = kt;
    }
    __syncthreads();

    if (b >= NEBLK) {
        // ---- build part ----
        const int s = b - NEBLK;
        float lo = (s == 0)         ? 0.f : fminf(fmaxf(srt[s - 1], 0.f), 1.f);
        float hi = (s == NBINS - 1) ? 1.f : fminf(fmaxf(srt[s], 0.f), 1.f);
        float m  = 0.5f * (lo + hi);
        if (t < 64) {
            float w = w1[t], bb = b1[t];
            bool act = (fmaf(m, w, bb) > 0.f);
            wa[t] = act ? w : 0.f;
            ba[t] = act ? bb : 0.f;
        }
        __syncthreads();
        for (int e = t; e < 1024; e += 256) {
            float p = 0.f, q = 0.f;
            #pragma unroll 8
            for (int j = 0; j < 64; j++) {
                float v = w2[j * 1024 + e];
                p = fmaf(wa[j], v, p);
                q = fmaf(ba[j], v, q);
            }
            g_P[s * 1024 + e] = p;
            g_Q[s * 1024 + e] = q + b2[e];
        }
        return;
    }

    // ---- hist part ----
    const int gid = b * EB + t;

    if (gid < N_NODES) {
        int bg = batch[gid];
        int bp = (gid > 0) ? batch[gid - 1] : -1;
        if (bg != bp) {
            g_gs[bg] = gid;
            if (gid > 0) g_ge[bp] = gid;
        }
        if (gid == N_NODES - 1) g_ge[bg] = N_NODES;
    }

    if (gid < N_EDGES) {
        float a = ea[gid];
        int pos = 0;
        #pragma unroll
        for (int step = 32; step >= 1; step >>= 1)
            if (srt[pos + step - 1] < a) pos += step;
        int r = atomicAdd(&lh[pos], 1);
        g_sr[gid] = pos | (r << 8);
    }
    __syncthreads();
    if (t < NBINS) g_bhist[t * NEBLK + b] = lh[t];
}

// ---------------- K2: per-bin exclusive scan + out init ----------------
__global__ void __launch_bounds__(256) bin_scan_kernel(
    float* __restrict__ out, const float* __restrict__ lin_b)
{
    __shared__ int wsum[8];
    __shared__ int total_sm;
    const int t = threadIdx.x;
    const int lane = t & 31, w = t >> 5;
    int* base = g_bhist + blockIdx.x * NEBLK;

    if (blockIdx.x == 0 && t < N_GRAPHS * 2) out[t] = lin_b[t & 1];

    const int beg = t * 4;
    int v[4];
    int local = 0;
    #pragma unroll
    for (int i = 0; i < 4; i++) {
        int idx = beg + i;
        v[i] = (idx < NEBLK) ? base[idx] : 0;
        local += v[i];
    }

    int incl = local;
    #pragma unroll
    for (int d = 1; d < 32; d <<= 1) {
        int y = __shfl_up_sync(0xffffffffu, incl, d);
        if (lane >= d) incl += y;
    }
    if (lane == 31) wsum[w] = incl;
    __syncthreads();
    if (t == 0) {
        int acc = 0;
        #pragma unroll
        for (int i = 0; i < 8; i++) { int q = wsum[i]; wsum[i] = acc; acc += q; }
        total_sm = acc;
    }
    __syncthreads();

    int carry = incl - local + wsum[w];
    #pragma unroll
    for (int i = 0; i < 4; i++) {
        int idx = beg + i;
        if (idx < NEBLK) { base[idx] = carry; carry += v[i]; }
    }
    if (t == 0) g_btot[blockIdx.x] = total_sm;
}

// ---------------- K3: deterministic scatter + degree counts ----------------
__global__ void __launch_bounds__(256) scatter_kernel(const int* __restrict__ ei)
{
    __shared__ int sbase[NBINS];
    const int t = threadIdx.x;
    if (t == 0) {
        int acc = 0;
        #pragma unroll
        for (int i = 0; i < NBINS; i++) { sbase[i] = acc; acc += g_btot[i]; }
    }
    __syncthreads();
    int e = blockIdx.x * EB + t;
    if (e < N_EDGES) {
        int sr = g_sr[e];
        int s = sr & 0xFF, r = sr >> 8;
        int pos = sbase[s] + g_bhist[s * NEBLK + blockIdx.x] + r;
        g_perm[pos] = e | (s << 18);
        atomicAdd(&g_cnt[ei[N_EDGES + e]], 1.f);
    }
}

// ---------------- K4: edge messages via tf32 MMA (R11-validated) ------------
// K-permuted layout: thread c0's A fragment = x[c0*8 .. c0*8+7] (contiguous,
// 2x LDG.128). B smem frag-row k sources P/Q physical row
// p(k) = (k&3)*8 + 2*((k>>3)&3) + ((k>>2)&1)  (per 32-row half).
__global__ void __launch_bounds__(256) edge2_kernel(
    const float* __restrict__ x, const int* __restrict__ ei,
    const float* __restrict__ ea)
{
    __shared__ unsigned sB[32 * 66];
    const int t = threadIdx.x;
    const int lane = t & 31, wrp = t >> 5;
    const int r0 = lane >> 2, c0 = lane & 3;
    const int base = blockIdx.x * EB;
    const int endidx = min(base + EB - 1, N_EDGES - 1);
    const int s_lo = g_perm[base] >> 18;
    const int s_hi = g_perm[endidx] >> 18;

    int dstv[4];
    int sse[4];
    unsigned af[4][8], xf[4][8];

    #pragma unroll
    for (int t4 = 0; t4 < 4; t4++) {
        int ridx = base + wrp * 32 + r0 + t4 * 8;
        bool v = (ridx < N_EDGES);
        int pk = g_perm[v ? ridx : endidx];
        int e = pk & 0x3FFFF;
        sse[t4] = v ? (pk >> 18) : -1;
        int src = ei[e];
        dstv[t4] = ei[N_EDGES + e];
        float a = ea[e];
        const float4* xp = (const float4*)(x + src * IN_F) + c0 * 2;
        float4 f0 = xp[0], f1 = xp[1];
        float xv[8] = {f0.x, f0.y, f0.z, f0.w, f1.x, f1.y, f1.z, f1.w};
        #pragma unroll
        for (int q = 0; q < 8; q++) {
            xf[t4][q] = f2tf32(xv[q]);
            af[t4][q] = f2tf32(a * xv[q]);
        }
    }

    const bool evenlane = ((c0 & 1) == 0);
    const int nq = (c0 & 2) * 2;

    for (int s = s_lo; s <= s_hi; s++) {
        bool mine = (sse[0] == s) | (sse[1] == s) | (sse[2] == s) | (sse[3] == s);
        if (!__syncthreads_or(mine ? 1 : 0)) continue;

        #pragma unroll
        for (int u = 0; u < 8; u++) {
            int idx = u * 256 + t;
            int k = idx >> 5, n = idx & 31;
            int kl = k & 31;
            int p = (kl & 3) * 8 + ((k >> 3) & 3) * 2 + ((kl >> 2) & 1);
            float v = (k < 32) ? g_P[s * 1024 + p * 32 + n]
                               : g_Q[s * 1024 + p * 32 + n];
            int kq = k >> 3, klow = k & 7;
            int c0p = klow & 3, hi = klow >> 2;
            sB[(kq * 4 + c0p) * 66 + n * 2 + hi] = f2tf32(v);
        }
        __syncthreads();

        float acc[2][4][4];
        #pragma unroll
        for (int nb = 0; nb < 4; nb++) {
            #pragma unroll
            for (int kq = 0; kq < 8; kq++) {
                uint2 b = *(const uint2*)&sB[(kq * 4 + c0) * 66 + (nb * 8 + r0) * 2];
                const int q0 = (2 * kq) & 7;
                const unsigned* F0 = (kq < 4) ? af[0] : xf[0];
                const unsigned* F1 = (kq < 4) ? af[1] : xf[1];
                const unsigned* F2 = (kq < 4) ? af[2] : xf[2];
                const unsigned* F3 = (kq < 4) ? af[3] : xf[3];
                if (kq == 0) {
                    MMA_SET(acc[0][nb], F0[q0], F1[q0], F0[q0 + 1], F1[q0 + 1], b.x, b.y);
                    MMA_SET(acc[1][nb], F2[q0], F3[q0], F2[q0 + 1], F3[q0 + 1], b.x, b.y);
                } else {
                    MMA_ACC(acc[0][nb], F0[q0], F1[q0], F0[q0 + 1], F1[q0 + 1], b.x, b.y);
                    MMA_ACC(acc[1][nb], F2[q0], F3[q0], F2[q0 + 1], F3[q0 + 1], b.x, b.y);
                }
            }
        }

        #pragma unroll
        for (int mt = 0; mt < 2; mt++) {
            const int te = mt * 2, to = mt * 2 + 1;
            #pragma unroll
            for (int nb = 0; nb < 4; nb++) {
                float send0 = evenlane ? acc[mt][nb][2] : acc[mt][nb][0];
                float send1 = evenlane ? acc[mt][nb][3] : acc[mt][nb][1];
                float recv0 = __shfl_xor_sync(0xffffffffu, send0, 1);
                float recv1 = __shfl_xor_sync(0xffffffffu, send1, 1);
                const int nbase = nb * 8 + nq;
                if (evenlane) {
                    if (sse[te] == s)
                        red_add_v4(&g_agg[dstv[te] * HID + nbase],
                                   acc[mt][nb][0], acc[mt][nb][1], recv0, recv1);
                } else {
                    if (sse[to] == s)
                        red_add_v4(&g_agg[dstv[to] * HID + nbase],
                                   recv0, recv1, acc[mt][nb][2], acc[mt][nb][3]);
                }
            }
        }
        __syncthreads();
    }
}

// ---------------- K5: node update + pooling + classifier + scratch restore --
__global__ void __launch_bounds__(256) node_kernel(
    const float* __restrict__ x, const int* __restrict__ batch,
    const float* __restrict__ root, const float* __restrict__ conv_bias,
    const float* __restrict__ lin_w, float* __restrict__ out)
{
    int wrp = threadIdx.x >> 5, lane = threadIdx.x & 31;
    int n0 = (blockIdx.x * 8 + wrp) * 8;
    if (n0 >= N_NODES) return;

    float rt[32];
    #pragma unroll
    for (int i = 0; i < IN_F; i++) rt[i] = root[i * HID + lane];
    const float cb = conv_bias[lane];
    const float lw0 = lin_w[lane * 2 + 0];
    const float lw1 = lin_w[lane * 2 + 1];

    float acc = 0.f;
    int gcur = batch[n0];
    #pragma unroll
    for (int k = 0; k < 8; k++) {
        int n = n0 + k;
        if (n >= N_NODES) break;
        int g = batch[n];
        if (g != gcur) {
            float s0 = acc * lw0, s1 = acc * lw1;
            #pragma unroll
            for (int d = 16; d > 0; d >>= 1) {
                s0 += __shfl_xor_sync(0xffffffffu, s0, d);
                s1 += __shfl_xor_sync(0xffffffffu, s1, d);
            }
            if (lane == 0) {
                float inv = 1.f / fmaxf((float)(g_ge[gcur] - g_gs[gcur]), 1.f);
                atomicAdd(&out[gcur * 2 + 0], s0 * inv);
                atomicAdd(&out[gcur * 2 + 1], s1 * inv);
            }
            acc = 0.f; gcur = g;
        }
        float av = g_agg[n * HID + lane];
        float c  = g_cnt[n];
        g_agg[n * HID + lane] = 0.f;         // restore scratch for next replay
        if (lane == 0) g_cnt[n] = 0.f;
        float vv = av / fmaxf(c, 1.f);
        float xv = x[n * IN_F + lane];
        float ss = 0.f;
        #pragma unroll
        for (int i = 0; i < IN_F; i++)
            ss = fmaf(__shfl_sync(0xffffffffu, xv, i), rt[i], ss);
        acc += fmaxf(vv + ss + cb, 0.f);
    }
    {
        float s0 = acc * lw0, s1 = acc * lw1;
        #pragma unroll
        for (int d = 16; d > 0; d >>= 1) {
            s0 += __shfl_xor_sync(0xffffffffu, s0, d);
            s1 += __shfl_xor_sync(0xffffffffu, s1, d);
        }
        if (lane == 0) {
            float inv = 1.f / fmaxf((float)(g_ge[gcur] - g_gs[gcur]), 1.f);
            atomicAdd(&out[gcur * 2 + 0], s0 * inv);
            atomicAdd(&out[gcur * 2 + 1], s1 * inv);
        }
    }
}

// ---------------- launcher ----------------
extern "C" void kernel_launch(void* const* d_in, const int* in_sizes, int n_in,
                              void* d_out, int out_size) {
    const float* x    = (const float*)d_in[0];
    const int*   ei   = (const int*)  d_in[1];
    const float* ea   = (const float*)d_in[2];
    const int*   bat  = (const int*)  d_in[3];
    const float* w1   = (const float*)d_in[4];
    const float* b1   = (const float*)d_in[5];
    const float* w2   = (const float*)d_in[6];
    const float* b2   = (const float*)d_in[7];
    const float* root = (const float*)d_in[8];
    const float* cb   = (const float*)d_in[9];
    const float* lw   = (const float*)d_in[10];
    const float* lb   = (const float*)d_in[11];
    float* out = (float*)d_out;

    histbuild_kernel<<<HB_BLOCKS, 256>>>(ea, bat, w1, b1, w2, b2);
    bin_scan_kernel<<<NBINS, 256>>>(out, lb);
    scatter_kernel<<<NEBLK, 256>>>(ei);
    edge2_kernel<<<NEBLK, 256>>>(x, ei, ea);
    node_kernel<<<(N_NODES + 63) / 64, 256>>>(x, bat, root, cb, lw, out);
}

// round 15
// speedup vs baseline: 2.2795x; 2.2795x over previous
#include <cuda_runtime.h>

#define N_NODES 50000
#define N_EDGES 200000
#define IN_F 32
#define HID 32
#define N_GRAPHS 64
#define NBINS 65
#define EB 256                 // edges per block
#define NEBLK ((N_EDGES + EB - 1) / EB)
#define HB_BLOCKS (NEBLK + NBINS)

// ---------------- scratch (no allocs allowed) ----------------
__device__ float g_agg[N_NODES * HID];
__device__ float g_cnt[N_NODES];
__device__ float g_P[NBINS * 1024];
__device__ float g_Q[NBINS * 1024];
__device__ int   g_bhist[NBINS * NEBLK];
__device__ int   g_btot[NBINS];
__device__ int   g_sr[N_EDGES];      // s | (local_rank << 8)
__device__ int   g_perm[N_EDGES];    // e | (s << 18)
__device__ int   g_gs[N_GRAPHS];     // written for every present graph each call
__device__ int   g_ge[N_GRAPHS];

__device__ __forceinline__ float inf_f() { return __int_as_float(0x7f800000); }
__device__ __forceinline__ float key_of(float w, float b) {
    return (w != 0.f) ? (-b / w) : inf_f();
}
__device__ __forceinline__ unsigned f2tf32(float f) {
    unsigned r;
    asm("cvt.rna.tf32.f32 %0, %1;" : "=r"(r) : "f"(f));
    return r;
}
__device__ __forceinline__ void red_add_v4(float* p, float a, float b, float c, float d) {
    asm volatile("red.global.add.v4.f32 [%0], {%1,%2,%3,%4};"
                 :: "l"(p), "f"(a), "f"(b), "f"(c), "f"(d) : "memory");
}

#define MMA_ACC(C, a0, a1, a2, a3, B0, B1)                                      \
    asm volatile("mma.sync.aligned.m16n8k8.row.col.f32.tf32.tf32.f32 "          \
                 "{%0,%1,%2,%3}, {%4,%5,%6,%7}, {%8,%9}, {%0,%1,%2,%3};"        \
                 : "+f"((C)[0]), "+f"((C)[1]), "+f"((C)[2]), "+f"((C)[3])       \
                 : "r"(a0), "r"(a1), "r"(a2), "r"(a3), "r"(B0), "r"(B1))

#define MMA_SET(C, a0, a1, a2, a3, B0, B1)                                      \
    asm volatile("mma.sync.aligned.m16n8k8.row.col.f32.tf32.tf32.f32 "          \
                 "{%0,%1,%2,%3}, {%4,%5,%6,%7}, {%8,%9}, {%10,%11,%12,%13};"    \
                 : "=f"((C)[0]), "=f"((C)[1]), "=f"((C)[2]), "=f"((C)[3])       \
                 : "r"(a0), "r"(a1), "r"(a2), "r"(a3), "r"(B0), "r"(B1),        \
                   "f"(0.f), "f"(0.f), "f"(0.f), "f"(0.f))

// ---------------- K1: fused hist + build (ONLY change vs R11) ---------------
// blocks [0, NEBLK): R11 hist_kernel body (zeroing + bounds + bin ids)
// blocks [NEBLK, NEBLK+NBINS): R11 build_kernel body (s = b - NEBLK)
// NOTE: no g_gs/g_ge pre-zeroing (would race with bounds writes when fused;
// unnecessary — every graph id occurs in batch, so all entries are written).
__global__ void __launch_bounds__(256) histbuild_kernel(
    const float* __restrict__ ea, const int* __restrict__ batch,
    const float* __restrict__ w1, const float* __restrict__ b1,
    const float* __restrict__ w2, const float* __restrict__ b2)
{
    __shared__ float key[64], srt[64], wa[64], ba[64];
    __shared__ int lh[NBINS];
    const int t = threadIdx.x;
    const int b = blockIdx.x;

    if (t < 64) key[t] = key_of(w1[t], b1[t]);
    if (t < NBINS) lh[t] = 0;
    __syncthreads();
    if (t < 64) {
        float kt = key[t];
        int r = 0;
        #pragma unroll
        for (int k = 0; k < 64; k++) {
            float kk = key[k];
            r += (kk < kt) || (kk == kt && k < t);
        }
        srt[r] = kt;
    }
    __syncthreads();

    if (b >= NEBLK) {
        // ---- build part (R11 build_kernel) ----
        const int s = b - NEBLK;
        float lo = (s == 0)         ? 0.f : fminf(fmaxf(srt[s - 1], 0.f), 1.f);
        float hi = (s == NBINS - 1) ? 1.f : fminf(fmaxf(srt[s], 0.f), 1.f);
        float m  = 0.5f * (lo + hi);
        if (t < 64) {
            float w = w1[t], bb = b1[t];
            bool act = (fmaf(m, w, bb) > 0.f);
            wa[t] = act ? w : 0.f;
            ba[t] = act ? bb : 0.f;
        }
        __syncthreads();
        for (int e = t; e < 1024; e += 256) {
            float p = 0.f, q = 0.f;
            #pragma unroll 8
            for (int j = 0; j < 64; j++) {
                float v = w2[j * 1024 + e];
                p = fmaf(wa[j], v, p);
                q = fmaf(ba[j], v, q);
            }
            g_P[s * 1024 + e] = p;
            g_Q[s * 1024 + e] = q + b2[e];
        }
        return;
    }

    // ---- hist part (R11 hist_kernel) ----
    const int gid = b * EB + t;

    // zero g_agg / g_cnt
    {
        float4 z = make_float4(0.f, 0.f, 0.f, 0.f);
        float4* aggp = (float4*)g_agg;
        for (int i = gid; i < N_NODES * HID / 4; i += NEBLK * EB) aggp[i] = z;
        if (gid < N_NODES) g_cnt[gid] = 0.f;
    }

    // graph boundary detection on sorted batch
    if (gid < N_NODES) {
        int bg = batch[gid];
        int bp = (gid > 0) ? batch[gid - 1] : -1;
        if (bg != bp) {
            g_gs[bg] = gid;
            if (gid > 0) g_ge[bp] = gid;
        }
        if (gid == N_NODES - 1) g_ge[bg] = N_NODES;
    }

    if (gid < N_EDGES) {
        float a = ea[gid];
        int pos = 0;
        #pragma unroll
        for (int step = 32; step >= 1; step >>= 1)
            if (srt[pos + step - 1] < a) pos += step;
        int r = atomicAdd(&lh[pos], 1);
        g_sr[gid] = pos | (r << 8);
    }
    __syncthreads();
    if (t < NBINS) g_bhist[t * NEBLK + b] = lh[t];
}

// ---------------- K2: per-bin exclusive scan + out init (R11) ---------------
__global__ void __launch_bounds__(256) bin_scan_kernel(
    float* __restrict__ out, const float* __restrict__ lin_b)
{
    __shared__ int wsum[8];
    __shared__ int total_sm;
    const int t = threadIdx.x;
    const int lane = t & 31, w = t >> 5;
    int* base = g_bhist + blockIdx.x * NEBLK;

    if (blockIdx.x == 0 && t < N_GRAPHS * 2) out[t] = lin_b[t & 1];

    const int beg = t * 4;
    int v[4];
    int local = 0;
    #pragma unroll
    for (int i = 0; i < 4; i++) {
        int idx = beg + i;
        v[i] = (idx < NEBLK) ? base[idx] : 0;
        local += v[i];
    }

    int incl = local;
    #pragma unroll
    for (int d = 1; d < 32; d <<= 1) {
        int y = __shfl_up_sync(0xffffffffu, incl, d);
        if (lane >= d) incl += y;
    }
    if (lane == 31) wsum[w] = incl;
    __syncthreads();
    if (t == 0) {
        int acc = 0;
        #pragma unroll
        for (int i = 0; i < 8; i++) { int q = wsum[i]; wsum[i] = acc; acc += q; }
        total_sm = acc;
    }
    __syncthreads();

    int carry = incl - local + wsum[w];
    #pragma unroll
    for (int i = 0; i < 4; i++) {
        int idx = beg + i;
        if (idx < NEBLK) { base[idx] = carry; carry += v[i]; }
    }
    if (t == 0) g_btot[blockIdx.x] = total_sm;
}

// ---------------- K3: deterministic scatter + degree counts (R11) -----------
__global__ void __launch_bounds__(256) scatter_kernel(const int* __restrict__ ei)
{
    __shared__ int sbase[NBINS];
    const int t = threadIdx.x;
    if (t == 0) {
        int acc = 0;
        #pragma unroll
        for (int i = 0; i < NBINS; i++) { sbase[i] = acc; acc += g_btot[i]; }
    }
    __syncthreads();
    int e = blockIdx.x * EB + t;
    if (e < N_EDGES) {
        int sr = g_sr[e];
        int s = sr & 0xFF, r = sr >> 8;
        int pos = sbase[s] + g_bhist[s * NEBLK + blockIdx.x] + r;
        g_perm[pos] = e | (s << 18);
        atomicAdd(&g_cnt[ei[N_EDGES + e]], 1.f);
    }
}

// ---------------- K4: edge messages via tf32 MMA (R11, byte-identical) ------
__global__ void __launch_bounds__(256) edge2_kernel(
    const float* __restrict__ x, const int* __restrict__ ei,
    const float* __restrict__ ea)
{
    __shared__ unsigned sB[32 * 66];
    const int t = threadIdx.x;
    const int lane = t & 31, wrp = t >> 5;
    const int r0 = lane >> 2, c0 = lane & 3;
    const int base = blockIdx.x * EB;
    const int endidx = min(base + EB - 1, N_EDGES - 1);
    const int s_lo = g_perm[base] >> 18;
    const int s_hi = g_perm[endidx] >> 18;

    int dstv[4];
    int sse[4];
    unsigned af[4][8], xf[4][8];

    #pragma unroll
    for (int t4 = 0; t4 < 4; t4++) {
        int ridx = base + wrp * 32 + r0 + t4 * 8;
        bool v = (ridx < N_EDGES);
        int pk = g_perm[v ? ridx : endidx];
        int e = pk & 0x3FFFF;
        sse[t4] = v ? (pk >> 18) : -1;
        int src = ei[e];
        dstv[t4] = ei[N_EDGES + e];
        float a = ea[e];
        const float4* xp = (const float4*)(x + src * IN_F) + c0 * 2;
        float4 f0 = xp[0], f1 = xp[1];
        float xv[8] = {f0.x, f0.y, f0.z, f0.w, f1.x, f1.y, f1.z, f1.w};
        #pragma unroll
        for (int q = 0; q < 8; q++) {
            xf[t4][q] = f2tf32(xv[q]);
            af[t4][q] = f2tf32(a * xv[q]);
        }
    }

    const bool evenlane = ((c0 & 1) == 0);
    const int nq = (c0 & 2) * 2;

    for (int s = s_lo; s <= s_hi; s++) {
        bool mine = (sse[0] == s) | (sse[1] == s) | (sse[2] == s) | (sse[3] == s);
        if (!__syncthreads_or(mine ? 1 : 0)) continue;

        #pragma unroll
        for (int u = 0; u < 8; u++) {
            int idx = u * 256 + t;
            int k = idx >> 5, n = idx & 31;
            int kl = k & 31;
            int p = (kl & 3) * 8 + ((k >> 3) & 3) * 2 + ((kl >> 2) & 1);
            float v = (k < 32) ? g_P[s * 1024 + p * 32 + n]
                               : g_Q[s * 1024 + p * 32 + n];
            int kq = k >> 3, klow = k & 7;
            int c0p = klow & 3, hi = klow >> 2;
            sB[(kq * 4 + c0p) * 66 + n * 2 + hi] = f2tf32(v);
        }
        __syncthreads();

        float acc[2][4][4];
        #pragma unroll
        for (int nb = 0; nb < 4; nb++) {
            #pragma unroll
            for (int kq = 0; kq < 8; kq++) {
                uint2 b = *(const uint2*)&sB[(kq * 4 + c0) * 66 + (nb * 8 + r0) * 2];
                const int q0 = (2 * kq) & 7;
                const unsigned* F0 = (kq < 4) ? af[0] : xf[0];
                const unsigned* F1 = (kq < 4) ? af[1] : xf[1];
                const unsigned* F2 = (kq < 4) ? af[2] : xf[2];
                const unsigned* F3 = (kq < 4) ? af[3] : xf[3];
                if (kq == 0) {
                    MMA_SET(acc[0][nb], F0[q0], F1[q0], F0[q0 + 1], F1[q0 + 1], b.x, b.y);
                    MMA_SET(acc[1][nb], F2[q0], F3[q0], F2[q0 + 1], F3[q0 + 1], b.x, b.y);
                } else {
                    MMA_ACC(acc[0][nb], F0[q0], F1[q0], F0[q0 + 1], F1[q0 + 1], b.x, b.y);
                    MMA_ACC(acc[1][nb], F2[q0], F3[q0], F2[q0 + 1], F3[q0 + 1], b.x, b.y);
                }
            }
        }

        #pragma unroll
        for (int mt = 0; mt < 2; mt++) {
            const int te = mt * 2, to = mt * 2 + 1;
            #pragma unroll
            for (int nb = 0; nb < 4; nb++) {
                float send0 = evenlane ? acc[mt][nb][2] : acc[mt][nb][0];
                float send1 = evenlane ? acc[mt][nb][3] : acc[mt][nb][1];
                float recv0 = __shfl_xor_sync(0xffffffffu, send0, 1);
                float recv1 = __shfl_xor_sync(0xffffffffu, send1, 1);
                const int nbase = nb * 8 + nq;
                if (evenlane) {
                    if (sse[te] == s)
                        red_add_v4(&g_agg[dstv[te] * HID + nbase],
                                   acc[mt][nb][0], acc[mt][nb][1], recv0, recv1);
                } else {
                    if (sse[to] == s)
                        red_add_v4(&g_agg[dstv[to] * HID + nbase],
                                   recv0, recv1, acc[mt][nb][2], acc[mt][nb][3]);
                }
            }
        }
        __syncthreads();
    }
}

// ---------------- K5: node update + pooling + classifier (R11, no restore) --
__global__ void __launch_bounds__(256) node_kernel(
    const float* __restrict__ x, const int* __restrict__ batch,
    const float* __restrict__ root, const float* __restrict__ conv_bias,
    const float* __restrict__ lin_w, float* __restrict__ out)
{
    int wrp = threadIdx.x >> 5, lane = threadIdx.x & 31;
    int n0 = (blockIdx.x * 8 + wrp) * 8;
    if (n0 >= N_NODES) return;

    float rt[32];
    #pragma unroll
    for (int i = 0; i < IN_F; i++) rt[i] = root[i * HID + lane];
    const float cb = conv_bias[lane];
    const float lw0 = lin_w[lane * 2 + 0];
    const float lw1 = lin_w[lane * 2 + 1];

    float acc = 0.f;
    int gcur = batch[n0];
    #pragma unroll
    for (int k = 0; k < 8; k++) {
        int n = n0 + k;
        if (n >= N_NODES) break;
        int g = batch[n];
        if (g != gcur) {
            float s0 = acc * lw0, s1 = acc * lw1;
            #pragma unroll
            for (int d = 16; d > 0; d >>= 1) {
                s0 += __shfl_xor_sync(0xffffffffu, s0, d);
                s1 += __shfl_xor_sync(0xffffffffu, s1, d);
            }
            if (lane == 0) {
                float inv = 1.f / fmaxf((float)(g_ge[gcur] - g_gs[gcur]), 1.f);
                atomicAdd(&out[gcur * 2 + 0], s0 * inv);
                atomicAdd(&out[gcur * 2 + 1], s1 * inv);
            }
            acc = 0.f; gcur = g;
        }
        float vv = g_agg[n * HID + lane] / fmaxf(g_cnt[n], 1.f);
        float xv = x[n * IN_F + lane];
        float ss = 0.f;
        #pragma unroll
        for (int i = 0; i < IN_F; i++)
            ss = fmaf(__shfl_sync(0xffffffffu, xv, i), rt[i], ss);
        acc += fmaxf(vv + ss + cb, 0.f);
    }
    {
        float s0 = acc * lw0, s1 = acc * lw1;
        #pragma unroll
        for (int d = 16; d > 0; d >>= 1) {
            s0 += __shfl_xor_sync(0xffffffffu, s0, d);
            s1 += __shfl_xor_sync(0xffffffffu, s1, d);
        }
        if (lane == 0) {
            float inv = 1.f / fmaxf((float)(g_ge[gcur] - g_gs[gcur]), 1.f);
            atomicAdd(&out[gcur * 2 + 0], s0 * inv);
            atomicAdd(&out[gcur * 2 + 1], s1 * inv);
        }
    }
}

// ---------------- launcher ----------------
extern "C" void kernel_launch(void* const* d_in, const int* in_sizes, int n_in,
                              void* d_out, int out_size) {
    const float* x    = (const float*)d_in[0];
    const int*   ei   = (const int*)  d_in[1];
    const float* ea   = (const float*)d_in[2];
    const int*   bat  = (const int*)  d_in[3];
    const float* w1   = (const float*)d_in[4];
    const float* b1   = (const float*)d_in[5];
    const float* w2   = (const float*)d_in[6];
    const float* b2   = (const float*)d_in[7];
    const float* root = (const float*)d_in[8];
    const float* cb   = (const float*)d_in[9];
    const float* lw   = (const float*)d_in[10];
    const float* lb   = (const float*)d_in[11];
    float* out = (float*)d_out;

    histbuild_kernel<<<HB_BLOCKS, 256>>>(ea, bat, w1, b1, w2, b2);
    bin_scan_kernel<<<NBINS, 256>>>(out, lb);
    scatter_kernel<<<NEBLK, 256>>>(ei);
    edge2_kernel<<<NEBLK, 256>>>(x, ei, ea);
    node_kernel<<<(N_NODES + 63) / 64, 256>>>(x, bat, root, cb, lw, out);
}